// round 14
// baseline (speedup 1.0000x reference)
#include <cuda_runtime.h>
#include <cuda_bf16.h>
#include <math.h>
#include <stdint.h>

#define BSZ 256        // batch B
#define NSEQ 4096      // K*B
#define H 64
#define G4 256
#define ZXD 320
#define LSTM_IN 322
#define TT 50

__device__ __forceinline__ float tanhg(float x) {
    float y;
    asm("tanh.approx.f32 %0, %1;" : "=f"(y) : "f"(x));
    return y;
}
__device__ __forceinline__ float sigg(float x) {
    return fmaf(0.5f, tanhg(0.5f * x), 0.5f);
}
__device__ __forceinline__ uint32_t f2tf(float x) {
    uint32_t r;
    asm("cvt.rna.tf32.f32 %0, %1;" : "=r"(r) : "f"(x));
    return r;
}
__device__ __forceinline__ uint32_t packbf2(float a, float b) {
    __nv_bfloat16 ha = __float2bfloat16(a), hb = __float2bfloat16(b);
    return (uint32_t)__bfloat16_as_ushort(ha)
         | ((uint32_t)__bfloat16_as_ushort(hb) << 16);
}

// m16n8k8 tf32 mma, D += A*B
__device__ __forceinline__ void mma8(float* d, const uint4& a,
                                     uint32_t b0, uint32_t b1) {
    asm volatile(
        "mma.sync.aligned.m16n8k8.row.col.f32.tf32.tf32.f32 "
        "{%0,%1,%2,%3}, {%4,%5,%6,%7}, {%8,%9}, {%0,%1,%2,%3};"
        : "+f"(d[0]), "+f"(d[1]), "+f"(d[2]), "+f"(d[3])
        : "r"(a.x), "r"(a.y), "r"(a.z), "r"(a.w), "r"(b0), "r"(b1));
}
// m16n8k16 bf16 mma, D += A*B
__device__ __forceinline__ void mma16(float* d, const uint4& a,
                                      uint32_t b0, uint32_t b1) {
    asm volatile(
        "mma.sync.aligned.m16n8k16.row.col.f32.bf16.bf16.f32 "
        "{%0,%1,%2,%3}, {%4,%5,%6,%7}, {%8,%9}, {%0,%1,%2,%3};"
        : "+f"(d[0]), "+f"(d[1]), "+f"(d[2]), "+f"(d[3])
        : "r"(a.x), "r"(a.y), "r"(a.z), "r"(a.w), "r"(b0), "r"(b1));
}

// scratch
__device__ float g_G0[NSEQ * G4];   // [n][u*4 + q]
__device__ float g_h0[NSEQ * H];
__device__ float g_c0[NSEQ * H];

// ---------------------------------------------------------------------------
// Phase 1 (unchanged):  [G0 | h0 | c0] = zx @ [Wih[:, :320] | Wh0 | Wc0]^T
// ---------------------------------------------------------------------------
__global__ __launch_bounds__(256) void phase1_kernel(
    const float* __restrict__ x, const float* __restrict__ z,
    const float* __restrict__ Wih, const float* __restrict__ Wh0,
    const float* __restrict__ Wc0,
    const float* __restrict__ bih, const float* __restrict__ bhh,
    const float* __restrict__ bh0, const float* __restrict__ bc0)
{
    __shared__ float As[16][68];
    __shared__ float Ws[16][68];
    const int tid = threadIdx.x;
    const int n0 = blockIdx.x * 64;
    const int c0 = blockIdx.y * 64;
    const int tx = tid & 15, ty = tid >> 4;
    float acc[4][4] = {};

    for (int kt = 0; kt < ZXD; kt += 16) {
        #pragma unroll
        for (int i = 0; i < 4; i++) {
            int e = tid + i * 256;
            int kk = e & 15, rr = e >> 4;
            int n = n0 + rr, m = kt + kk;
            float v = (m < H) ? z[n * H + m]
                              : x[(n & (BSZ - 1)) * 256 + (m - H)];
            As[kk][rr] = v;
        }
        #pragma unroll
        for (int i = 0; i < 4; i++) {
            int e = tid + i * 256;
            int kk = e & 15, cc = e >> 4;
            int j = c0 + cc, m = kt + kk;
            float v;
            if (j < G4)          v = Wih[j * LSTM_IN + m];
            else if (j < G4 + H) v = Wh0[(j - G4) * ZXD + m];
            else                 v = Wc0[(j - G4 - H) * ZXD + m];
            Ws[kk][cc] = v;
        }
        __syncthreads();
        #pragma unroll
        for (int kk = 0; kk < 16; kk++) {
            float a[4], b[4];
            #pragma unroll
            for (int i = 0; i < 4; i++) a[i] = As[kk][ty * 4 + i];
            #pragma unroll
            for (int j = 0; j < 4; j++) b[j] = Ws[kk][tx * 4 + j];
            #pragma unroll
            for (int i = 0; i < 4; i++)
                #pragma unroll
                for (int j = 0; j < 4; j++)
                    acc[i][j] += a[i] * b[j];
        }
        __syncthreads();
    }

    #pragma unroll
    for (int i = 0; i < 4; i++) {
        int n = n0 + ty * 4 + i;
        #pragma unroll
        for (int j = 0; j < 4; j++) {
            int col = c0 + tx * 4 + j;
            float v = acc[i][j];
            if (col < G4) {
                int u = col & 63, q = col >> 6;
                g_G0[n * G4 + u * 4 + q] = v + bih[col] + bhh[col];
            }
            else if (col < G4 + H) g_h0[n * H + (col - G4)]     = v + bh0[col - G4];
            else                   g_c0[n * H + (col - G4 - H)] = v + bc0[col - G4 - H];
        }
    }
}

// ---------------------------------------------------------------------------
// Phase 2: R13 pipeline at 512 threads (16 warps, 4/SMSP).
// warp w: gates n-tiles {2w, 2w+1}  ->  thread = 4 seqs x 1 unit
//   (unit u0 = 8*(w>>1) + 2*(lane&3) + (w&1))
// heads: warps 0..11, one n-tile each.  GMM: 512 threads = 32 seqs x 16 comps.
// 3 barriers/step.
// ---------------------------------------------------------------------------
#define SM_BG   0                       // 32nt*5kt*32*4 = 20480 w
#define SM_BHD  20480                   // 12nt*9kt*32*2 = 6912 w
#define SM_ABH  27392                   // 5kt*2mt*32*4 = 1280 w
#define SM_ABL  28672                   // 1280 w
#define SM_AT   29952                   // 9kt*2mt*32*4 = 2304 w
#define SM_PO   32256                   // 32*100 = 3200 w
#define SM_DT   35456                   // 64 w
#define SM_TOT  35520
#define SMEM_BYTES (SM_TOT * 4)
#define NTH 512

__global__ __launch_bounds__(NTH, 1) void phase2_kernel(
    const float* __restrict__ inp_seqs, const float* __restrict__ pred_seqs,
    const float* __restrict__ Whh, const float* __restrict__ Wih,
    const float* __restrict__ Wpi, const float* __restrict__ bpi,
    const float* __restrict__ Wmu, const float* __restrict__ bmu,
    const float* __restrict__ Wls, const float* __restrict__ bls,
    const float* __restrict__ Wcorr, const float* __restrict__ bcorr,
    float* __restrict__ out)
{
    extern __shared__ float sm[];
    uint32_t* smu = (uint32_t*)sm;
    const int tid  = threadIdx.x;
    const int lane = tid & 31;
    const int warp = tid >> 5;        // 0..15
    const int nb   = blockIdx.x * 32;
    const int m4   = lane & 3;
    const int sr   = lane >> 2;

    // ---- zero A regions ----
    for (int e = tid; e < 1280 * 2 + 2304; e += NTH) sm[SM_ABH + e] = 0.f;

    // ---- stage B gates: bf16 hi/lo, fragment-major, permuted cols ----
    for (int e = tid; e < 256 * 80; e += NTH) {
        int j = e / 80, k = e - (e / 80) * 80;
        int w = j >> 5, i = (j >> 3) & 3, m = (j >> 1) & 3, b = j & 1;
        int u = 8 * w + 2 * m + (i >> 1);
        int q = 2 * (i & 1) + b;
        int row = q * 64 + u;
        float v = 0.f;
        if (k < 64)       v = Whh[row * 64 + k];
        else if (k == 64) v = Wih[row * LSTM_IN + 320];
        else if (k == 65) v = Wih[row * LSTM_IN + 321];
        __nv_bfloat16 hb = __float2bfloat16(v);
        __nv_bfloat16 lb = __float2bfloat16(v - __bfloat162float(hb));
        int nt = j >> 3, kt = k >> 4, kk = k & 15;
        int lanep = (j & 7) * 4 + ((kk >> 1) & 3);
        int breg = kk >> 3, half = kk & 1;
        char* p = (char*)(smu + SM_BG)
                  + (((nt * 5 + kt) * 32 + lanep) * 4 + breg) * 4 + half * 2;
        *(__nv_bfloat16*)p       = hb;
        *(__nv_bfloat16*)(p + 8) = lb;
    }
    // ---- stage B heads (single tf32, bias at k=66) ----
    for (int e = tid; e < 96 * 72; e += NTH) {
        int jj = e / 72, k = e - (e / 72) * 72;
        float v = 0.f;
        if (k < 64) {
            if (jj < 16)      v = Wpi[jj * 64 + k];
            else if (jj < 48) v = Wmu[(jj - 16) * 64 + k];
            else if (jj < 80) v = Wls[(jj - 48) * 64 + k];
            else              v = Wcorr[(jj - 80) * 64 + k];
        } else if (k == 66) {
            if (jj < 16)      v = bpi[jj];
            else if (jj < 48) v = bmu[jj - 16];
            else if (jj < 80) v = bls[jj - 48];
            else              v = bcorr[jj - 80];
        }
        int nt = jj >> 3, kt = k >> 3, kl = k & 7;
        int lanep = (jj & 7) * 4 + (kl & 3);
        int r = kl >> 2;
        smu[SM_BHD + ((nt * 9 + kt) * 32 + lanep) * 2 + r] = f2tf(v);
    }
    __syncthreads();   // zeros done before partial A fills

    // ---- stage A: h0 -> bf16 (hi+lo) and tf32 (hi) ----
    for (int e = tid; e < 32 * 64; e += NTH) {
        int s = e >> 6, k = e & 63;
        float v = g_h0[(nb + s) * 64 + k];
        // bf16
        {
            __nv_bfloat16 hb = __float2bfloat16(v);
            __nv_bfloat16 lb = __float2bfloat16(v - __bfloat162float(hb));
            int mt = s >> 4, rr = s & 15, kt = k >> 4, kk = k & 15;
            int lanew = (rr & 7) * 4 + ((kk >> 1) & 3);
            int reg = (rr >> 3) + 2 * (kk >> 3);
            int half = kk & 1;
            int byteoff = (((kt * 2 + mt) * 32 + lanew) * 4 + reg) * 4 + half * 2;
            *(__nv_bfloat16*)((char*)(smu + SM_ABH) + byteoff) = hb;
            *(__nv_bfloat16*)((char*)(smu + SM_ABL) + byteoff) = lb;
        }
        // tf32
        {
            int mt = s >> 4, kt = k >> 3;
            int lanep = (s & 7) * 4 + (k & 3);
            int r = ((s >> 3) & 1) + 2 * ((k >> 2) & 1);
            smu[SM_AT + ((kt * 2 + mt) * 32 + lanep) * 4 + r] = f2tf(v);
        }
    }
    // ---- stage A: d0 (bf16) + const-1 (tf32, k=66) ----
    if (tid < 32) {
        int s = tid;
        int b = (nb + s) & (BSZ - 1);
        float dx = inp_seqs[(b * 8 + 7) * 24 + 20];
        float dy = inp_seqs[(b * 8 + 7) * 24 + 21];
        int mt = s >> 4, rr = s & 15;
        int idx = (((4 * 2 + mt) * 32 + (rr & 7) * 4) * 4 + (rr >> 3));
        __nv_bfloat16 hx = __float2bfloat16(dx), hy = __float2bfloat16(dy);
        float rx = dx - __bfloat162float(hx), ry = dy - __bfloat162float(hy);
        smu[SM_ABH + idx] = packbf2(dx, dy);
        smu[SM_ABL + idx] = packbf2(rx, ry);
        // tf32 const-1 at k=66
        int lanep = (s & 7) * 4 + (66 & 3);
        int r = ((s >> 3) & 1) + 2 * ((66 >> 2) & 1);
        smu[SM_AT + (((66 >> 3) * 2 + mt) * 32 + lanep) * 4 + r] = f2tf(1.0f);
    }

    // ---- per-thread identity: unit u0, 4 seqs ----
    const int wp = warp >> 1;          // 0..7
    const int ip = warp & 1;           // unit offset
    const int u0 = 8 * wp + 2 * m4 + ip;

    // register state: G0 + c for 4 seqs x 1 unit
    float G0r[4][4];
    float c[4];
    #pragma unroll
    for (int j = 0; j < 4; j++) {
        int s = sr + (j & 1) * 8 + (j >> 1) * 16;
        int n = nb + s;
        float4 g0 = *(const float4*)(g_G0 + n * 256 + u0 * 4);
        G0r[j][0] = g0.x; G0r[j][1] = g0.y;
        G0r[j][2] = g0.z; G0r[j][3] = g0.w;
        c[j] = g_c0[n * 64 + u0];
    }

    const int b_mine = (nb + lane) & (BSZ - 1);
    const int sh = lane >> 4;
    const int gc = lane & 15;
    float lacc = 0.f;

    const uint4* abh = (const uint4*)(smu + SM_ABH) + lane;
    const uint4* abl = (const uint4*)(smu + SM_ABL) + lane;
    const uint4* atp = (const uint4*)(smu + SM_AT) + lane;
    const uint4* bgp = (const uint4*)(smu + SM_BG) + (2 * warp * 5) * 32 + lane;
    const uint2* bhp = (const uint2*)(smu + SM_BHD) + (warp * 9) * 32 + lane;

    // per-thread h-write constants
    const int kt2 = u0 >> 4;
    const int kkh = u0 & 15;
    const int lane_w = (kkh >> 1) & 3;
    const int reg_b = 2 * (kkh >> 3);
    const int half_b = kkh & 1;
    const int ktt = u0 >> 3;
    const int rtw = 2 * ((u0 >> 2) & 1);

    __syncthreads();

    for (int t = 1; t <= TT; t++) {
        // prefetch pred row t-1 (decode for t+1 AND GMM target for t)
        float pdx = 0.f, pdy = 0.f;
        if (tid < 32) {
            const float* pr = pred_seqs + (b_mine * TT + (t - 1)) * 24 + 20;
            pdx = pr[0];
            pdy = pr[1];
        }

        // ======== gates MMA: bf16 3-term (60 mma16/warp) ========
        float acc[2][2][4];
        #pragma unroll
        for (int a = 0; a < 2; a++)
            #pragma unroll
            for (int b = 0; b < 2; b++)
                #pragma unroll
                for (int r = 0; r < 4; r++) acc[a][b][r] = 0.f;

        #pragma unroll
        for (int kt = 0; kt < 5; kt++) {
            uint4 ah0 = abh[(kt * 2 + 0) * 32];
            uint4 ah1 = abh[(kt * 2 + 1) * 32];
            uint4 al0 = abl[(kt * 2 + 0) * 32];
            uint4 al1 = abl[(kt * 2 + 1) * 32];
            #pragma unroll
            for (int i2 = 0; i2 < 2; i2++) {
                uint4 B = bgp[(i2 * 5 + kt) * 32];
                mma16(acc[i2][0], ah0, B.x, B.y);
                mma16(acc[i2][1], ah1, B.x, B.y);
                mma16(acc[i2][0], al0, B.x, B.y);
                mma16(acc[i2][1], al1, B.x, B.y);
                mma16(acc[i2][0], ah0, B.z, B.w);
                mma16(acc[i2][1], ah1, B.z, B.w);
            }
        }

        // ======== pointwise LSTM (registers): 4 seqs x 1 unit ========
        float hreg[4];
        #pragma unroll
        for (int j = 0; j < 4; j++) {
            int mt = j >> 1, rh = j & 1;
            float gi = acc[0][mt][2 * rh + 0] + G0r[j][0];
            float gf = acc[0][mt][2 * rh + 1] + G0r[j][1];
            float gg = acc[1][mt][2 * rh + 0] + G0r[j][2];
            float go = acc[1][mt][2 * rh + 1] + G0r[j][3];
            float cc = sigg(gf) * c[j] + sigg(gi) * tanhg(gg);
            c[j] = cc;
            hreg[j] = sigg(go) * tanhg(cc);
        }
        __syncthreads();   // all A reads done

        // ======== write h (bf16 hi/lo halves + tf32) + d(t+1) + DT ========
        #pragma unroll
        for (int j = 0; j < 4; j++) {
            int mt = j >> 1;
            int s = sr + (j & 1) * 8 + mt * 16;
            int rr = s & 15;
            float hv = hreg[j];
            // bf16 (16-bit halves)
            {
                __nv_bfloat16 hb = __float2bfloat16(hv);
                __nv_bfloat16 lb = __float2bfloat16(hv - __bfloat162float(hb));
                int lanew = (rr & 7) * 4 + lane_w;
                int reg = (rr >> 3) + reg_b;
                int byteoff = (((kt2 * 2 + mt) * 32 + lanew) * 4 + reg) * 4
                              + half_b * 2;
                *(__nv_bfloat16*)((char*)(smu + SM_ABH) + byteoff) = hb;
                *(__nv_bfloat16*)((char*)(smu + SM_ABL) + byteoff) = lb;
            }
            // tf32
            {
                int lanep = (s & 7) * 4 + (u0 & 3);
                int r = ((s >> 3) & 1) + rtw;
                smu[SM_AT + ((ktt * 2 + mt) * 32 + lanep) * 4 + r] = f2tf(hv);
            }
        }
        if (tid < 32) {
            int s = lane;
            sm[SM_DT + s * 2]     = pdx;
            sm[SM_DT + s * 2 + 1] = pdy;
            int mt = s >> 4, rr = s & 15;
            int idx = (((4 * 2 + mt) * 32 + (rr & 7) * 4) * 4 + (rr >> 3));
            float rx, ry;
            {
                __nv_bfloat16 hx = __float2bfloat16(pdx);
                __nv_bfloat16 hy = __float2bfloat16(pdy);
                rx = pdx - __bfloat162float(hx);
                ry = pdy - __bfloat162float(hy);
            }
            smu[SM_ABH + idx] = packbf2(pdx, pdy);
            smu[SM_ABL + idx] = packbf2(rx, ry);
        }
        __syncthreads();   // new A + DT visible

        // ======== heads MMA (warps 0-11, one n-tile each, tf32) ========
        if (warp < 12) {
            float facc[2][4];
            #pragma unroll
            for (int b = 0; b < 2; b++)
                #pragma unroll
                for (int r = 0; r < 4; r++) facc[b][r] = 0.f;
            #pragma unroll
            for (int kt = 0; kt < 9; kt++) {
                uint4 ah0 = atp[(kt * 2 + 0) * 32];
                uint4 ah1 = atp[(kt * 2 + 1) * 32];
                uint2 Bh = bhp[kt * 32];
                mma8(facc[0], ah0, Bh.x, Bh.y);
                mma8(facc[1], ah1, Bh.x, Bh.y);
            }
            int jc = 8 * warp + 2 * m4;
            #pragma unroll
            for (int mt = 0; mt < 2; mt++) {
                int r0 = sr + 16 * mt;
                *(float2*)(sm + SM_PO + r0 * 100 + jc) =
                    make_float2(facc[mt][0], facc[mt][1]);
                *(float2*)(sm + SM_PO + (r0 + 8) * 100 + jc) =
                    make_float2(facc[mt][2], facc[mt][3]);
            }
        }
        __syncthreads();   // Po visible

        // ======== GMM + LSE: 512 threads = 32 seqs x 16 comps, one pass ====
        {
            int gs = 2 * warp + sh;
            float txv = sm[SM_DT + gs * 2];
            float tyv = sm[SM_DT + gs * 2 + 1];
            const float* pr = sm + SM_PO + gs * 100;
            float pi  = pr[gc];
            float2 mu  = *(const float2*)(pr + 16 + 2 * gc);
            float2 lsv = *(const float2*)(pr + 48 + 2 * gc);
            float corr = tanhg(pr[80 + gc]);
            float ls0 = fminf(fmaxf(lsv.x, -10.f), 10.f);
            float ls1 = fminf(fmaxf(lsv.y, -10.f), 10.f);
            float dx = txv - mu.x, dy = tyv - mu.y;
            float z0 = dx * __expf(-ls0);
            float z1 = dy * __expf(-ls1);
            float omr  = 1.f - corr * corr;
            float quad = z0 * z0 + z1 * z1 - 2.f * corr * z0 * z1;
            float cv = -1.8378770664093453f - (ls0 + ls1)
                       - 0.5f * __logf(omr) - 0.5f * __fdividef(quad, omr);
            float a = pi + cv;
            float b2 = pi;
            float ma = a, mb = b2;
            #pragma unroll
            for (int xm = 1; xm < 16; xm <<= 1) {
                ma = fmaxf(ma, __shfl_xor_sync(0xFFFFFFFFu, ma, xm));
                mb = fmaxf(mb, __shfl_xor_sync(0xFFFFFFFFu, mb, xm));
            }
            float ea = __expf(a - ma);
            float eb = __expf(b2 - mb);
            #pragma unroll
            for (int xm = 1; xm < 16; xm <<= 1) {
                ea += __shfl_xor_sync(0xFFFFFFFFu, ea, xm);
                eb += __shfl_xor_sync(0xFFFFFFFFu, eb, xm);
            }
            float lp = (ma + __logf(ea)) - (mb + __logf(eb));
            lacc += fminf(lp, 50.f);
        }
        // no trailing barrier: DT/Po rewritten only after next step's barriers
    }

    if ((lane & 15) == 0) out[nb + 2 * warp + sh] = lacc;
}

// ---------------------------------------------------------------------------
extern "C" void kernel_launch(void* const* d_in, const int* in_sizes, int n_in,
                              void* d_out, int out_size)
{
    const float* x      = (const float*)d_in[0];
    const float* z      = (const float*)d_in[1];
    const float* inps   = (const float*)d_in[2];
    const float* preds  = (const float*)d_in[3];
    const float* Wh0    = (const float*)d_in[4];
    const float* bh0    = (const float*)d_in[5];
    const float* Wc0    = (const float*)d_in[6];
    const float* bc0    = (const float*)d_in[7];
    const float* Wih    = (const float*)d_in[8];
    const float* Whh    = (const float*)d_in[9];
    const float* bih    = (const float*)d_in[10];
    const float* bhh    = (const float*)d_in[11];
    const float* Wpi    = (const float*)d_in[12];
    const float* bpi    = (const float*)d_in[13];
    const float* Wmu    = (const float*)d_in[14];
    const float* bmu    = (const float*)d_in[15];
    const float* Wls    = (const float*)d_in[16];
    const float* bls    = (const float*)d_in[17];
    const float* Wcorr  = (const float*)d_in[18];
    const float* bcorr  = (const float*)d_in[19];
    float* out = (float*)d_out;

    cudaFuncSetAttribute(phase2_kernel,
                         cudaFuncAttributeMaxDynamicSharedMemorySize, SMEM_BYTES);

    dim3 g1(NSEQ / 64, 384 / 64);
    phase1_kernel<<<g1, 256>>>(x, z, Wih, Wh0, Wc0, bih, bhh, bh0, bc0);

    phase2_kernel<<<NSEQ / 32, NTH, SMEM_BYTES>>>(
        inps, preds, Whh, Wih,
        Wpi, bpi, Wmu, bmu, Wls, bls, Wcorr, bcorr, out);
}

// round 15
// speedup vs baseline: 1.0358x; 1.0358x over previous
#include <cuda_runtime.h>
#include <cuda_bf16.h>
#include <math.h>
#include <stdint.h>

#define BSZ 256        // batch B
#define NSEQ 4096      // K*B
#define H 64
#define G4 256
#define ZXD 320
#define LSTM_IN 322
#define TT 50

__device__ __forceinline__ float tanhg(float x) {
    float y;
    asm("tanh.approx.f32 %0, %1;" : "=f"(y) : "f"(x));
    return y;
}
__device__ __forceinline__ float sigg(float x) {
    return fmaf(0.5f, tanhg(0.5f * x), 0.5f);
}
__device__ __forceinline__ uint32_t f2tf(float x) {
    uint32_t r;
    asm("cvt.rna.tf32.f32 %0, %1;" : "=r"(r) : "f"(x));
    return r;
}
__device__ __forceinline__ uint32_t packbf2(float a, float b) {
    __nv_bfloat16 ha = __float2bfloat16(a), hb = __float2bfloat16(b);
    return (uint32_t)__bfloat16_as_ushort(ha)
         | ((uint32_t)__bfloat16_as_ushort(hb) << 16);
}

// m16n8k8 tf32 mma, D += A*B
__device__ __forceinline__ void mma8(float* d, const uint4& a,
                                     uint32_t b0, uint32_t b1) {
    asm volatile(
        "mma.sync.aligned.m16n8k8.row.col.f32.tf32.tf32.f32 "
        "{%0,%1,%2,%3}, {%4,%5,%6,%7}, {%8,%9}, {%0,%1,%2,%3};"
        : "+f"(d[0]), "+f"(d[1]), "+f"(d[2]), "+f"(d[3])
        : "r"(a.x), "r"(a.y), "r"(a.z), "r"(a.w), "r"(b0), "r"(b1));
}
// m16n8k16 bf16 mma, D += A*B
__device__ __forceinline__ void mma16(float* d, const uint4& a,
                                      uint32_t b0, uint32_t b1) {
    asm volatile(
        "mma.sync.aligned.m16n8k16.row.col.f32.bf16.bf16.f32 "
        "{%0,%1,%2,%3}, {%4,%5,%6,%7}, {%8,%9}, {%0,%1,%2,%3};"
        : "+f"(d[0]), "+f"(d[1]), "+f"(d[2]), "+f"(d[3])
        : "r"(a.x), "r"(a.y), "r"(a.z), "r"(a.w), "r"(b0), "r"(b1));
}

// scratch
__device__ float g_G0[NSEQ * G4];   // [n][u*4 + q]
__device__ float g_h0[NSEQ * H];
__device__ float g_c0[NSEQ * H];

// ---------------------------------------------------------------------------
// Phase 1 (NEW): bf16 hi/lo 3-term mma GEMM.
// C[4096 x 384] = zx[4096 x 320] @ [Wih[:, :320] | Wh0 | Wc0]^T  (+ biases)
// Block: 128 seqs x 96 cols, 256 threads (8 warps; warp = m16 tile x 12 nt).
// K staged in 5 chunks of 64 (4 k16-tiles) through smem fragments.
// ---------------------------------------------------------------------------
#define P1_AH  0                        // 4kt*8mt*32 uint4 = 4096 w
#define P1_AL  4096                     // 4096 w
#define P1_B   8192                     // 4kt*12nt*32 uint4 = 6144 w
#define P1_TOT 14336
#define SMEM1 (P1_TOT * 4)

__global__ __launch_bounds__(256, 1) void phase1_kernel(
    const float* __restrict__ x, const float* __restrict__ z,
    const float* __restrict__ Wih, const float* __restrict__ Wh0,
    const float* __restrict__ Wc0,
    const float* __restrict__ bih, const float* __restrict__ bhh,
    const float* __restrict__ bh0, const float* __restrict__ bc0)
{
    extern __shared__ float sm[];
    uint32_t* smu = (uint32_t*)sm;
    const int tid  = threadIdx.x;
    const int lane = tid & 31;
    const int warp = tid >> 5;        // 0..7 = m-tile
    const int nb   = blockIdx.x * 128;
    const int cb   = blockIdx.y * 96;

    float facc[12][4];
    #pragma unroll
    for (int nt = 0; nt < 12; nt++)
        #pragma unroll
        for (int r = 0; r < 4; r++) facc[nt][r] = 0.f;

    for (int ch = 0; ch < 5; ch++) {
        // ---- stage A chunk: zx[128][64] bf16 hi/lo frags ----
        for (int e = tid; e < 128 * 64; e += 256) {
            int r = e >> 6, kl = e & 63;
            int kg = ch * 64 + kl;
            float v = (kg < H) ? z[(nb + r) * H + kg]
                               : x[((nb + r) & (BSZ - 1)) * 256 + (kg - H)];
            __nv_bfloat16 hb = __float2bfloat16(v);
            __nv_bfloat16 lb = __float2bfloat16(v - __bfloat162float(hb));
            int kt = kl >> 4, kk = kl & 15, mt = r >> 4, rr = r & 15;
            int lanew = (rr & 7) * 4 + ((kk >> 1) & 3);
            int reg = (rr >> 3) + 2 * (kk >> 3);
            int byteoff = (((kt * 8 + mt) * 32 + lanew) * 4 + reg) * 4
                          + (kk & 1) * 2;
            *(__nv_bfloat16*)((char*)(smu + P1_AH) + byteoff) = hb;
            *(__nv_bfloat16*)((char*)(smu + P1_AL) + byteoff) = lb;
        }
        // ---- stage B chunk: W[96][64] bf16 hi/lo packed uint4 ----
        for (int e = tid; e < 96 * 64; e += 256) {
            int jj = e >> 6, kl = e & 63;
            int kg = ch * 64 + kl;
            int j = cb + jj;
            float v;
            if (j < G4)          v = Wih[j * LSTM_IN + kg];
            else if (j < G4 + H) v = Wh0[(j - G4) * ZXD + kg];
            else                 v = Wc0[(j - G4 - H) * ZXD + kg];
            __nv_bfloat16 hb = __float2bfloat16(v);
            __nv_bfloat16 lb = __float2bfloat16(v - __bfloat162float(hb));
            int kt = kl >> 4, kk = kl & 15, nt = jj >> 3;
            int lanep = (jj & 7) * 4 + ((kk >> 1) & 3);
            int breg = kk >> 3;
            char* p = (char*)(smu + P1_B)
                      + (((kt * 12 + nt) * 32 + lanep) * 4 + breg) * 4
                      + (kk & 1) * 2;
            *(__nv_bfloat16*)p       = hb;
            *(__nv_bfloat16*)(p + 8) = lb;
        }
        __syncthreads();

        // ---- compute: 4 kt x 12 nt x 3-term ----
        #pragma unroll
        for (int kt = 0; kt < 4; kt++) {
            uint4 ah = *(const uint4*)(smu + P1_AH
                        + ((kt * 8 + warp) * 32 + lane) * 4);
            uint4 al = *(const uint4*)(smu + P1_AL
                        + ((kt * 8 + warp) * 32 + lane) * 4);
            #pragma unroll
            for (int nt = 0; nt < 12; nt++) {
                uint4 B = *(const uint4*)(smu + P1_B
                            + ((kt * 12 + nt) * 32 + lane) * 4);
                mma16(facc[nt], ah, B.x, B.y);
                mma16(facc[nt], al, B.x, B.y);
                mma16(facc[nt], ah, B.z, B.w);
            }
        }
        __syncthreads();
    }

    // ---- epilogue: scatter with biases ----
    #pragma unroll
    for (int nt = 0; nt < 12; nt++) {
        int jc = cb + 8 * nt + 2 * (lane & 3);
        #pragma unroll
        for (int rh = 0; rh < 2; rh++) {
            int n = nb + 16 * warp + (lane >> 2) + 8 * rh;
            #pragma unroll
            for (int cc = 0; cc < 2; cc++) {
                int j = jc + cc;
                float v = facc[nt][2 * rh + cc];
                if (j < G4) {
                    int u = j & 63, q = j >> 6;
                    g_G0[n * G4 + u * 4 + q] = v + bih[j] + bhh[j];
                } else if (j < G4 + H) {
                    g_h0[n * H + (j - G4)] = v + bh0[j - G4];
                } else {
                    g_c0[n * H + (j - G4 - H)] = v + bc0[j - G4 - H];
                }
            }
        }
    }
}

// ---------------------------------------------------------------------------
// Phase 2 (unchanged from R14): bf16-k16 gates + tf32 heads, 512 threads.
// ---------------------------------------------------------------------------
#define SM_BG   0                       // 32nt*5kt*32*4 = 20480 w
#define SM_BHD  20480                   // 12nt*9kt*32*2 = 6912 w
#define SM_ABH  27392                   // 5kt*2mt*32*4 = 1280 w
#define SM_ABL  28672                   // 1280 w
#define SM_AT   29952                   // 9kt*2mt*32*4 = 2304 w
#define SM_PO   32256                   // 32*100 = 3200 w
#define SM_DT   35456                   // 64 w
#define SM_TOT  35520
#define SMEM_BYTES (SM_TOT * 4)
#define NTH 512

__global__ __launch_bounds__(NTH, 1) void phase2_kernel(
    const float* __restrict__ inp_seqs, const float* __restrict__ pred_seqs,
    const float* __restrict__ Whh, const float* __restrict__ Wih,
    const float* __restrict__ Wpi, const float* __restrict__ bpi,
    const float* __restrict__ Wmu, const float* __restrict__ bmu,
    const float* __restrict__ Wls, const float* __restrict__ bls,
    const float* __restrict__ Wcorr, const float* __restrict__ bcorr,
    float* __restrict__ out)
{
    extern __shared__ float sm[];
    uint32_t* smu = (uint32_t*)sm;
    const int tid  = threadIdx.x;
    const int lane = tid & 31;
    const int warp = tid >> 5;        // 0..15
    const int nb   = blockIdx.x * 32;
    const int m4   = lane & 3;
    const int sr   = lane >> 2;

    // ---- zero A regions ----
    for (int e = tid; e < 1280 * 2 + 2304; e += NTH) sm[SM_ABH + e] = 0.f;

    // ---- stage B gates: bf16 hi/lo, fragment-major, permuted cols ----
    for (int e = tid; e < 256 * 80; e += NTH) {
        int j = e / 80, k = e - (e / 80) * 80;
        int w = j >> 5, i = (j >> 3) & 3, m = (j >> 1) & 3, b = j & 1;
        int u = 8 * w + 2 * m + (i >> 1);
        int q = 2 * (i & 1) + b;
        int row = q * 64 + u;
        float v = 0.f;
        if (k < 64)       v = Whh[row * 64 + k];
        else if (k == 64) v = Wih[row * LSTM_IN + 320];
        else if (k == 65) v = Wih[row * LSTM_IN + 321];
        __nv_bfloat16 hb = __float2bfloat16(v);
        __nv_bfloat16 lb = __float2bfloat16(v - __bfloat162float(hb));
        int nt = j >> 3, kt = k >> 4, kk = k & 15;
        int lanep = (j & 7) * 4 + ((kk >> 1) & 3);
        int breg = kk >> 3, half = kk & 1;
        char* p = (char*)(smu + SM_BG)
                  + (((nt * 5 + kt) * 32 + lanep) * 4 + breg) * 4 + half * 2;
        *(__nv_bfloat16*)p       = hb;
        *(__nv_bfloat16*)(p + 8) = lb;
    }
    // ---- stage B heads (single tf32, bias at k=66) ----
    for (int e = tid; e < 96 * 72; e += NTH) {
        int jj = e / 72, k = e - (e / 72) * 72;
        float v = 0.f;
        if (k < 64) {
            if (jj < 16)      v = Wpi[jj * 64 + k];
            else if (jj < 48) v = Wmu[(jj - 16) * 64 + k];
            else if (jj < 80) v = Wls[(jj - 48) * 64 + k];
            else              v = Wcorr[(jj - 80) * 64 + k];
        } else if (k == 66) {
            if (jj < 16)      v = bpi[jj];
            else if (jj < 48) v = bmu[jj - 16];
            else if (jj < 80) v = bls[jj - 48];
            else              v = bcorr[jj - 80];
        }
        int nt = jj >> 3, kt = k >> 3, kl = k & 7;
        int lanep = (jj & 7) * 4 + (kl & 3);
        int r = kl >> 2;
        smu[SM_BHD + ((nt * 9 + kt) * 32 + lanep) * 2 + r] = f2tf(v);
    }
    __syncthreads();   // zeros done before partial A fills

    // ---- stage A: h0 -> bf16 (hi+lo) and tf32 (hi) ----
    for (int e = tid; e < 32 * 64; e += NTH) {
        int s = e >> 6, k = e & 63;
        float v = g_h0[(nb + s) * 64 + k];
        {
            __nv_bfloat16 hb = __float2bfloat16(v);
            __nv_bfloat16 lb = __float2bfloat16(v - __bfloat162float(hb));
            int mt = s >> 4, rr = s & 15, kt = k >> 4, kk = k & 15;
            int lanew = (rr & 7) * 4 + ((kk >> 1) & 3);
            int reg = (rr >> 3) + 2 * (kk >> 3);
            int half = kk & 1;
            int byteoff = (((kt * 2 + mt) * 32 + lanew) * 4 + reg) * 4 + half * 2;
            *(__nv_bfloat16*)((char*)(smu + SM_ABH) + byteoff) = hb;
            *(__nv_bfloat16*)((char*)(smu + SM_ABL) + byteoff) = lb;
        }
        {
            int mt = s >> 4, kt = k >> 3;
            int lanep = (s & 7) * 4 + (k & 3);
            int r = ((s >> 3) & 1) + 2 * ((k >> 2) & 1);
            smu[SM_AT + ((kt * 2 + mt) * 32 + lanep) * 4 + r] = f2tf(v);
        }
    }
    // ---- stage A: d0 (bf16) + const-1 (tf32, k=66) ----
    if (tid < 32) {
        int s = tid;
        int b = (nb + s) & (BSZ - 1);
        float dx = inp_seqs[(b * 8 + 7) * 24 + 20];
        float dy = inp_seqs[(b * 8 + 7) * 24 + 21];
        int mt = s >> 4, rr = s & 15;
        int idx = (((4 * 2 + mt) * 32 + (rr & 7) * 4) * 4 + (rr >> 3));
        __nv_bfloat16 hx = __float2bfloat16(dx), hy = __float2bfloat16(dy);
        float rx = dx - __bfloat162float(hx), ry = dy - __bfloat162float(hy);
        smu[SM_ABH + idx] = packbf2(dx, dy);
        smu[SM_ABL + idx] = packbf2(rx, ry);
        int lanep = (s & 7) * 4 + (66 & 3);
        int r = ((s >> 3) & 1) + 2 * ((66 >> 2) & 1);
        smu[SM_AT + (((66 >> 3) * 2 + mt) * 32 + lanep) * 4 + r] = f2tf(1.0f);
    }

    // ---- per-thread identity: unit u0, 4 seqs ----
    const int wp = warp >> 1;
    const int ip = warp & 1;
    const int u0 = 8 * wp + 2 * m4 + ip;

    float G0r[4][4];
    float c[4];
    #pragma unroll
    for (int j = 0; j < 4; j++) {
        int s = sr + (j & 1) * 8 + (j >> 1) * 16;
        int n = nb + s;
        float4 g0 = *(const float4*)(g_G0 + n * 256 + u0 * 4);
        G0r[j][0] = g0.x; G0r[j][1] = g0.y;
        G0r[j][2] = g0.z; G0r[j][3] = g0.w;
        c[j] = g_c0[n * 64 + u0];
    }

    const int b_mine = (nb + lane) & (BSZ - 1);
    const int sh = lane >> 4;
    const int gc = lane & 15;
    float lacc = 0.f;

    const uint4* abh = (const uint4*)(smu + SM_ABH) + lane;
    const uint4* abl = (const uint4*)(smu + SM_ABL) + lane;
    const uint4* atp = (const uint4*)(smu + SM_AT) + lane;
    const uint4* bgp = (const uint4*)(smu + SM_BG) + (2 * warp * 5) * 32 + lane;
    const uint2* bhp = (const uint2*)(smu + SM_BHD) + (warp * 9) * 32 + lane;

    const int kt2 = u0 >> 4;
    const int kkh = u0 & 15;
    const int lane_w = (kkh >> 1) & 3;
    const int reg_b = 2 * (kkh >> 3);
    const int half_b = kkh & 1;
    const int ktt = u0 >> 3;
    const int rtw = 2 * ((u0 >> 2) & 1);

    __syncthreads();

    for (int t = 1; t <= TT; t++) {
        float pdx = 0.f, pdy = 0.f;
        if (tid < 32) {
            const float* pr = pred_seqs + (b_mine * TT + (t - 1)) * 24 + 20;
            pdx = pr[0];
            pdy = pr[1];
        }

        // ======== gates MMA: bf16 3-term (60 mma16/warp) ========
        float acc[2][2][4];
        #pragma unroll
        for (int a = 0; a < 2; a++)
            #pragma unroll
            for (int b = 0; b < 2; b++)
                #pragma unroll
                for (int r = 0; r < 4; r++) acc[a][b][r] = 0.f;

        #pragma unroll
        for (int kt = 0; kt < 5; kt++) {
            uint4 ah0 = abh[(kt * 2 + 0) * 32];
            uint4 ah1 = abh[(kt * 2 + 1) * 32];
            uint4 al0 = abl[(kt * 2 + 0) * 32];
            uint4 al1 = abl[(kt * 2 + 1) * 32];
            #pragma unroll
            for (int i2 = 0; i2 < 2; i2++) {
                uint4 B = bgp[(i2 * 5 + kt) * 32];
                mma16(acc[i2][0], ah0, B.x, B.y);
                mma16(acc[i2][1], ah1, B.x, B.y);
                mma16(acc[i2][0], al0, B.x, B.y);
                mma16(acc[i2][1], al1, B.x, B.y);
                mma16(acc[i2][0], ah0, B.z, B.w);
                mma16(acc[i2][1], ah1, B.z, B.w);
            }
        }

        // ======== pointwise LSTM: 4 seqs x 1 unit ========
        float hreg[4];
        #pragma unroll
        for (int j = 0; j < 4; j++) {
            int mt = j >> 1, rh = j & 1;
            float gi = acc[0][mt][2 * rh + 0] + G0r[j][0];
            float gf = acc[0][mt][2 * rh + 1] + G0r[j][1];
            float gg = acc[1][mt][2 * rh + 0] + G0r[j][2];
            float go = acc[1][mt][2 * rh + 1] + G0r[j][3];
            float cc = sigg(gf) * c[j] + sigg(gi) * tanhg(gg);
            c[j] = cc;
            hreg[j] = sigg(go) * tanhg(cc);
        }
        __syncthreads();   // all A reads done

        // ======== write h (bf16 halves + tf32) + d(t+1) + DT ========
        #pragma unroll
        for (int j = 0; j < 4; j++) {
            int mt = j >> 1;
            int s = sr + (j & 1) * 8 + mt * 16;
            int rr = s & 15;
            float hv = hreg[j];
            {
                __nv_bfloat16 hb = __float2bfloat16(hv);
                __nv_bfloat16 lb = __float2bfloat16(hv - __bfloat162float(hb));
                int lanew = (rr & 7) * 4 + lane_w;
                int reg = (rr >> 3) + reg_b;
                int byteoff = (((kt2 * 2 + mt) * 32 + lanew) * 4 + reg) * 4
                              + half_b * 2;
                *(__nv_bfloat16*)((char*)(smu + SM_ABH) + byteoff) = hb;
                *(__nv_bfloat16*)((char*)(smu + SM_ABL) + byteoff) = lb;
            }
            {
                int lanep = (s & 7) * 4 + (u0 & 3);
                int r = ((s >> 3) & 1) + rtw;
                smu[SM_AT + ((ktt * 2 + mt) * 32 + lanep) * 4 + r] = f2tf(hv);
            }
        }
        if (tid < 32) {
            int s = lane;
            sm[SM_DT + s * 2]     = pdx;
            sm[SM_DT + s * 2 + 1] = pdy;
            int mt = s >> 4, rr = s & 15;
            int idx = (((4 * 2 + mt) * 32 + (rr & 7) * 4) * 4 + (rr >> 3));
            float rx, ry;
            {
                __nv_bfloat16 hx = __float2bfloat16(pdx);
                __nv_bfloat16 hy = __float2bfloat16(pdy);
                rx = pdx - __bfloat162float(hx);
                ry = pdy - __bfloat162float(hy);
            }
            smu[SM_ABH + idx] = packbf2(pdx, pdy);
            smu[SM_ABL + idx] = packbf2(rx, ry);
        }
        __syncthreads();   // new A + DT visible

        // ======== heads MMA (warps 0-11, one n-tile each, tf32) ========
        if (warp < 12) {
            float facc2[2][4];
            #pragma unroll
            for (int b = 0; b < 2; b++)
                #pragma unroll
                for (int r = 0; r < 4; r++) facc2[b][r] = 0.f;
            #pragma unroll
            for (int kt = 0; kt < 9; kt++) {
                uint4 ah0 = atp[(kt * 2 + 0) * 32];
                uint4 ah1 = atp[(kt * 2 + 1) * 32];
                uint2 Bh = bhp[kt * 32];
                mma8(facc2[0], ah0, Bh.x, Bh.y);
                mma8(facc2[1], ah1, Bh.x, Bh.y);
            }
            int jc = 8 * warp + 2 * m4;
            #pragma unroll
            for (int mt = 0; mt < 2; mt++) {
                int r0 = sr + 16 * mt;
                *(float2*)(sm + SM_PO + r0 * 100 + jc) =
                    make_float2(facc2[mt][0], facc2[mt][1]);
                *(float2*)(sm + SM_PO + (r0 + 8) * 100 + jc) =
                    make_float2(facc2[mt][2], facc2[mt][3]);
            }
        }
        __syncthreads();   // Po visible

        // ======== GMM + LSE: 512 threads = 32 seqs x 16 comps ========
        {
            int gs = 2 * warp + sh;
            float txv = sm[SM_DT + gs * 2];
            float tyv = sm[SM_DT + gs * 2 + 1];
            const float* pr = sm + SM_PO + gs * 100;
            float pi  = pr[gc];
            float2 mu  = *(const float2*)(pr + 16 + 2 * gc);
            float2 lsv = *(const float2*)(pr + 48 + 2 * gc);
            float corr = tanhg(pr[80 + gc]);
            float ls0 = fminf(fmaxf(lsv.x, -10.f), 10.f);
            float ls1 = fminf(fmaxf(lsv.y, -10.f), 10.f);
            float dx = txv - mu.x, dy = tyv - mu.y;
            float z0 = dx * __expf(-ls0);
            float z1 = dy * __expf(-ls1);
            float omr  = 1.f - corr * corr;
            float quad = z0 * z0 + z1 * z1 - 2.f * corr * z0 * z1;
            float cv = -1.8378770664093453f - (ls0 + ls1)
                       - 0.5f * __logf(omr) - 0.5f * __fdividef(quad, omr);
            float a = pi + cv;
            float b2 = pi;
            float ma = a, mb = b2;
            #pragma unroll
            for (int xm = 1; xm < 16; xm <<= 1) {
                ma = fmaxf(ma, __shfl_xor_sync(0xFFFFFFFFu, ma, xm));
                mb = fmaxf(mb, __shfl_xor_sync(0xFFFFFFFFu, mb, xm));
            }
            float ea = __expf(a - ma);
            float eb = __expf(b2 - mb);
            #pragma unroll
            for (int xm = 1; xm < 16; xm <<= 1) {
                ea += __shfl_xor_sync(0xFFFFFFFFu, ea, xm);
                eb += __shfl_xor_sync(0xFFFFFFFFu, eb, xm);
            }
            float lp = (ma + __logf(ea)) - (mb + __logf(eb));
            lacc += fminf(lp, 50.f);
        }
    }

    if ((lane & 15) == 0) out[nb + 2 * warp + sh] = lacc;
}

// ---------------------------------------------------------------------------
extern "C" void kernel_launch(void* const* d_in, const int* in_sizes, int n_in,
                              void* d_out, int out_size)
{
    const float* x      = (const float*)d_in[0];
    const float* z      = (const float*)d_in[1];
    const float* inps   = (const float*)d_in[2];
    const float* preds  = (const float*)d_in[3];
    const float* Wh0    = (const float*)d_in[4];
    const float* bh0    = (const float*)d_in[5];
    const float* Wc0    = (const float*)d_in[6];
    const float* bc0    = (const float*)d_in[7];
    const float* Wih    = (const float*)d_in[8];
    const float* Whh    = (const float*)d_in[9];
    const float* bih    = (const float*)d_in[10];
    const float* bhh    = (const float*)d_in[11];
    const float* Wpi    = (const float*)d_in[12];
    const float* bpi    = (const float*)d_in[13];
    const float* Wmu    = (const float*)d_in[14];
    const float* bmu    = (const float*)d_in[15];
    const float* Wls    = (const float*)d_in[16];
    const float* bls    = (const float*)d_in[17];
    const float* Wcorr  = (const float*)d_in[18];
    const float* bcorr  = (const float*)d_in[19];
    float* out = (float*)d_out;

    cudaFuncSetAttribute(phase1_kernel,
                         cudaFuncAttributeMaxDynamicSharedMemorySize, SMEM1);
    cudaFuncSetAttribute(phase2_kernel,
                         cudaFuncAttributeMaxDynamicSharedMemorySize, SMEM_BYTES);

    dim3 g1(NSEQ / 128, 384 / 96);
    phase1_kernel<<<g1, 256, SMEM1>>>(x, z, Wih, Wh0, Wc0, bih, bhh, bh0, bc0);

    phase2_kernel<<<NSEQ / 32, NTH, SMEM_BYTES>>>(
        inps, preds, Whh, Wih,
        Wpi, bpi, Wmu, bmu, Wls, bls, Wcorr, bcorr, out);
}

// round 17
// speedup vs baseline: 1.0817x; 1.0444x over previous
#include <cuda_runtime.h>
#include <cuda_bf16.h>
#include <math.h>
#include <stdint.h>

#define BSZ 256        // batch B
#define NSEQ 4096      // K*B
#define H 64
#define G4 256
#define ZXD 320
#define LSTM_IN 322
#define TT 50

__device__ __forceinline__ float tanhg(float x) {
    float y;
    asm("tanh.approx.f32 %0, %1;" : "=f"(y) : "f"(x));
    return y;
}
__device__ __forceinline__ float sigg(float x) {
    return fmaf(0.5f, tanhg(0.5f * x), 0.5f);
}
__device__ __forceinline__ uint32_t packbf2(float a, float b) {
    __nv_bfloat16 ha = __float2bfloat16(a), hb = __float2bfloat16(b);
    return (uint32_t)__bfloat16_as_ushort(ha)
         | ((uint32_t)__bfloat16_as_ushort(hb) << 16);
}

// m16n8k16 bf16 mma, D += A*B
__device__ __forceinline__ void mma16(float* d, const uint4& a,
                                      uint32_t b0, uint32_t b1) {
    asm volatile(
        "mma.sync.aligned.m16n8k16.row.col.f32.bf16.bf16.f32 "
        "{%0,%1,%2,%3}, {%4,%5,%6,%7}, {%8,%9}, {%0,%1,%2,%3};"
        : "+f"(d[0]), "+f"(d[1]), "+f"(d[2]), "+f"(d[3])
        : "r"(a.x), "r"(a.y), "r"(a.z), "r"(a.w), "r"(b0), "r"(b1));
}

// scratch
__device__ float g_G0[NSEQ * G4];   // [n][u*4 + q]
__device__ float g_h0[NSEQ * H];
__device__ float g_c0[NSEQ * H];

// ---------------------------------------------------------------------------
// Phase 1 (R15, unchanged): bf16 hi/lo 3-term mma GEMM for [G0 | h0 | c0].
// ---------------------------------------------------------------------------
#define P1_AH  0
#define P1_AL  4096
#define P1_B   8192
#define P1_TOT 14336
#define SMEM1 (P1_TOT * 4)

__global__ __launch_bounds__(256, 1) void phase1_kernel(
    const float* __restrict__ x, const float* __restrict__ z,
    const float* __restrict__ Wih, const float* __restrict__ Wh0,
    const float* __restrict__ Wc0,
    const float* __restrict__ bih, const float* __restrict__ bhh,
    const float* __restrict__ bh0, const float* __restrict__ bc0)
{
    extern __shared__ float sm[];
    uint32_t* smu = (uint32_t*)sm;
    const int tid  = threadIdx.x;
    const int lane = tid & 31;
    const int warp = tid >> 5;
    const int nb   = blockIdx.x * 128;
    const int cb   = blockIdx.y * 96;

    float facc[12][4];
    #pragma unroll
    for (int nt = 0; nt < 12; nt++)
        #pragma unroll
        for (int r = 0; r < 4; r++) facc[nt][r] = 0.f;

    for (int ch = 0; ch < 5; ch++) {
        for (int e = tid; e < 128 * 64; e += 256) {
            int r = e >> 6, kl = e & 63;
            int kg = ch * 64 + kl;
            float v = (kg < H) ? z[(nb + r) * H + kg]
                               : x[((nb + r) & (BSZ - 1)) * 256 + (kg - H)];
            __nv_bfloat16 hb = __float2bfloat16(v);
            __nv_bfloat16 lb = __float2bfloat16(v - __bfloat162float(hb));
            int kt = kl >> 4, kk = kl & 15, mt = r >> 4, rr = r & 15;
            int lanew = (rr & 7) * 4 + ((kk >> 1) & 3);
            int reg = (rr >> 3) + 2 * (kk >> 3);
            int byteoff = (((kt * 8 + mt) * 32 + lanew) * 4 + reg) * 4
                          + (kk & 1) * 2;
            *(__nv_bfloat16*)((char*)(smu + P1_AH) + byteoff) = hb;
            *(__nv_bfloat16*)((char*)(smu + P1_AL) + byteoff) = lb;
        }
        for (int e = tid; e < 96 * 64; e += 256) {
            int jj = e >> 6, kl = e & 63;
            int kg = ch * 64 + kl;
            int j = cb + jj;
            float v;
            if (j < G4)          v = Wih[j * LSTM_IN + kg];
            else if (j < G4 + H) v = Wh0[(j - G4) * ZXD + kg];
            else                 v = Wc0[(j - G4 - H) * ZXD + kg];
            __nv_bfloat16 hb = __float2bfloat16(v);
            __nv_bfloat16 lb = __float2bfloat16(v - __bfloat162float(hb));
            int kt = kl >> 4, kk = kl & 15, nt = jj >> 3;
            int lanep = (jj & 7) * 4 + ((kk >> 1) & 3);
            int breg = kk >> 3;
            char* p = (char*)(smu + P1_B)
                      + (((kt * 12 + nt) * 32 + lanep) * 4 + breg) * 4
                      + (kk & 1) * 2;
            *(__nv_bfloat16*)p       = hb;
            *(__nv_bfloat16*)(p + 8) = lb;
        }
        __syncthreads();

        #pragma unroll
        for (int kt = 0; kt < 4; kt++) {
            uint4 ah = *(const uint4*)(smu + P1_AH
                        + ((kt * 8 + warp) * 32 + lane) * 4);
            uint4 al = *(const uint4*)(smu + P1_AL
                        + ((kt * 8 + warp) * 32 + lane) * 4);
            #pragma unroll
            for (int nt = 0; nt < 12; nt++) {
                uint4 B = *(const uint4*)(smu + P1_B
                            + ((kt * 12 + nt) * 32 + lane) * 4);
                mma16(facc[nt], ah, B.x, B.y);
                mma16(facc[nt], al, B.x, B.y);
                mma16(facc[nt], ah, B.z, B.w);
            }
        }
        __syncthreads();
    }

    #pragma unroll
    for (int nt = 0; nt < 12; nt++) {
        int jc = cb + 8 * nt + 2 * (lane & 3);
        #pragma unroll
        for (int rh = 0; rh < 2; rh++) {
            int n = nb + 16 * warp + (lane >> 2) + 8 * rh;
            #pragma unroll
            for (int cc = 0; cc < 2; cc++) {
                int j = jc + cc;
                float v = facc[nt][2 * rh + cc];
                if (j < G4) {
                    int u = j & 63, q = j >> 6;
                    g_G0[n * G4 + u * 4 + q] = v + bih[j] + bhh[j];
                } else if (j < G4 + H) {
                    g_h0[n * H + (j - G4)] = v + bh0[j - G4];
                } else {
                    g_c0[n * H + (j - G4 - H)] = v + bc0[j - G4 - H];
                }
            }
        }
    }
}

// ---------------------------------------------------------------------------
// Phase 2: 512 threads, 2 barriers/step, heads share gates' A fragments.
// u0 = 8*(w>>1) + 4*(w&1) + m4  (lane pairs own adjacent units -> word STS)
// gates: bf16 hi/lo 3-term; heads: bf16 hi/lo 3-term at lag-1 (in-loop),
// const-1 at A k=66 folds head bias. GMM lag-1, DT 2-slot ring.
// ---------------------------------------------------------------------------
#define SM_BG   0                       // 32nt*5kt*32*4 = 20480 w
#define SM_BH2  20480                   // 12nt*5kt*32*4 = 7680 w
#define SM_ABH  28160                   // 1280 w
#define SM_ABL  29440                   // 1280 w
#define SM_PO   30720                   // 32*100 = 3200 w
#define SM_DT   33920                   // [2][32][2] = 128 w
#define SM_TOT  34048
#define SMEM_BYTES (SM_TOT * 4)
#define NTH 512

__global__ __launch_bounds__(NTH, 1) void phase2_kernel(
    const float* __restrict__ inp_seqs, const float* __restrict__ pred_seqs,
    const float* __restrict__ Whh, const float* __restrict__ Wih,
    const float* __restrict__ Wpi, const float* __restrict__ bpi,
    const float* __restrict__ Wmu, const float* __restrict__ bmu,
    const float* __restrict__ Wls, const float* __restrict__ bls,
    const float* __restrict__ Wcorr, const float* __restrict__ bcorr,
    float* __restrict__ out)
{
    extern __shared__ float sm[];
    uint32_t* smu = (uint32_t*)sm;
    const int tid  = threadIdx.x;
    const int lane = tid & 31;
    const int warp = tid >> 5;        // 0..15
    const int nb   = blockIdx.x * 32;
    const int m4   = lane & 3;
    const int sr   = lane >> 2;

    // ---- zero A regions ----
    for (int e = tid; e < 2560; e += NTH) sm[SM_ABH + e] = 0.f;

    // ---- stage B gates: bf16 hi/lo, fragment-major, permuted cols ----
    // col j -> unit u = 8*(nt>>2) + 4*((nt>>1)&1) + ((j>>1)&3), gate q = 2*(nt&1)+(j&1)
    for (int e = tid; e < 256 * 80; e += NTH) {
        int j = e / 80, k = e - (e / 80) * 80;
        int nt = j >> 3;
        int u = 8 * (nt >> 2) + 4 * ((nt >> 1) & 1) + ((j >> 1) & 3);
        int q = 2 * (nt & 1) + (j & 1);
        int row = q * 64 + u;
        float v = 0.f;
        if (k < 64)       v = Whh[row * 64 + k];
        else if (k == 64) v = Wih[row * LSTM_IN + 320];
        else if (k == 65) v = Wih[row * LSTM_IN + 321];
        __nv_bfloat16 hb = __float2bfloat16(v);
        __nv_bfloat16 lb = __float2bfloat16(v - __bfloat162float(hb));
        int kt = k >> 4, kk = k & 15;
        int lanep = (j & 7) * 4 + ((kk >> 1) & 3);
        int breg = kk >> 3, half = kk & 1;
        char* p = (char*)(smu + SM_BG)
                  + (((nt * 5 + kt) * 32 + lanep) * 4 + breg) * 4 + half * 2;
        *(__nv_bfloat16*)p       = hb;
        *(__nv_bfloat16*)(p + 8) = lb;
    }
    // ---- stage B heads: bf16 hi/lo, bias folded at k=66 ----
    for (int e = tid; e < 96 * 80; e += NTH) {
        int jj = e / 80, k = e - (e / 80) * 80;
        float v = 0.f;
        if (k < 64) {
            if (jj < 16)      v = Wpi[jj * 64 + k];
            else if (jj < 48) v = Wmu[(jj - 16) * 64 + k];
            else if (jj < 80) v = Wls[(jj - 48) * 64 + k];
            else              v = Wcorr[(jj - 80) * 64 + k];
        } else if (k == 66) {
            if (jj < 16)      v = bpi[jj];
            else if (jj < 48) v = bmu[jj - 16];
            else if (jj < 80) v = bls[jj - 48];
            else              v = bcorr[jj - 80];
        }
        __nv_bfloat16 hb = __float2bfloat16(v);
        __nv_bfloat16 lb = __float2bfloat16(v - __bfloat162float(hb));
        int nt = jj >> 3, kt = k >> 4, kk = k & 15;
        int lanep = (jj & 7) * 4 + ((kk >> 1) & 3);
        int breg = kk >> 3, half = kk & 1;
        char* p = (char*)(smu + SM_BH2)
                  + (((nt * 5 + kt) * 32 + lanep) * 4 + breg) * 4 + half * 2;
        *(__nv_bfloat16*)p       = hb;
        *(__nv_bfloat16*)(p + 8) = lb;
    }
    __syncthreads();   // zeros done before partial A fills

    // ---- stage A: h0 (bf16 hi+lo) ----
    for (int e = tid; e < 32 * 64; e += NTH) {
        int s = e >> 6, k = e & 63;
        float v = g_h0[(nb + s) * 64 + k];
        __nv_bfloat16 hb = __float2bfloat16(v);
        __nv_bfloat16 lb = __float2bfloat16(v - __bfloat162float(hb));
        int mt = s >> 4, rr = s & 15, kt = k >> 4, kk = k & 15;
        int lanew = (rr & 7) * 4 + ((kk >> 1) & 3);
        int reg = (rr >> 3) + 2 * (kk >> 3);
        int half = kk & 1;
        int byteoff = (((kt * 2 + mt) * 32 + lanew) * 4 + reg) * 4 + half * 2;
        *(__nv_bfloat16*)((char*)(smu + SM_ABH) + byteoff) = hb;
        *(__nv_bfloat16*)((char*)(smu + SM_ABL) + byteoff) = lb;
    }
    // ---- stage A: d0 (k=64,65) + const-1 (k=66) ----
    if (tid < 32) {
        int s = tid;
        int b = (nb + s) & (BSZ - 1);
        float dx = inp_seqs[(b * 8 + 7) * 24 + 20];
        float dy = inp_seqs[(b * 8 + 7) * 24 + 21];
        int mt = s >> 4, rr = s & 15;
        int idxd = (((4 * 2 + mt) * 32 + (rr & 7) * 4) * 4 + (rr >> 3));
        float rx, ry;
        {
            __nv_bfloat16 hx = __float2bfloat16(dx);
            __nv_bfloat16 hy = __float2bfloat16(dy);
            rx = dx - __bfloat162float(hx);
            ry = dy - __bfloat162float(hy);
        }
        smu[SM_ABH + idxd] = packbf2(dx, dy);
        smu[SM_ABL + idxd] = packbf2(rx, ry);
        int idxc = (((4 * 2 + mt) * 32 + (rr & 7) * 4 + 1) * 4 + (rr >> 3));
        smu[SM_ABH + idxc] = packbf2(1.0f, 0.0f);
        // lo stays zero
    }

    // ---- per-thread identity ----
    const int wp = warp >> 1;
    const int ip = warp & 1;
    const int u0 = 8 * wp + 4 * ip + m4;

    float G0r[4][4];
    float c[4];
    #pragma unroll
    for (int j = 0; j < 4; j++) {
        int s = sr + (j & 1) * 8 + (j >> 1) * 16;
        int n = nb + s;
        float4 g0 = *(const float4*)(g_G0 + n * 256 + u0 * 4);
        G0r[j][0] = g0.x; G0r[j][1] = g0.y;
        G0r[j][2] = g0.z; G0r[j][3] = g0.w;
        c[j] = g_c0[n * 64 + u0];
    }

    const int b_mine = (nb + lane) & (BSZ - 1);
    const int sh = lane >> 4;
    const int gc = lane & 15;
    float lacc = 0.f;

    const uint4* abh = (const uint4*)(smu + SM_ABH) + lane;
    const uint4* abl = (const uint4*)(smu + SM_ABL) + lane;
    const uint4* bgp = (const uint4*)(smu + SM_BG) + (2 * warp * 5) * 32 + lane;
    const uint4* bh2 = (const uint4*)(smu + SM_BH2) + (warp * 5) * 32 + lane;

    // h-write word constants (unit pair base = u0 & ~1; even m4 lanes store)
    const int ub = u0 & ~1;
    const int kt2 = ub >> 4;
    const int kkw = (ub & 15) >> 1;
    const int lane_w = kkw & 3;
    const int reg_b = 2 * (kkw >> 2);

    __syncthreads();

    for (int i = 1; i <= TT + 1; i++) {
        // prefetch pred row i-1 (decode for step i+1, GMM target for step i)
        float pdx = 0.f, pdy = 0.f;
        if (tid < 32 && i <= TT) {
            const float* pr = pred_seqs + (b_mine * TT + (i - 1)) * 24 + 20;
            pdx = pr[0];
            pdy = pr[1];
        }
        const bool gt = (i <= TT);
        const bool hd = (warp < 12) && (i >= 2);

        // ======== phase 1: gates(i) + heads(h_{i-1}) on shared A frags ======
        float acc[2][2][4];
        float facc[2][4];
        if (hd) {
            #pragma unroll
            for (int b = 0; b < 2; b++)
                #pragma unroll
                for (int r = 0; r < 4; r++) facc[b][r] = 0.f;
        }
        if (gt) {
            #pragma unroll
            for (int a = 0; a < 2; a++)
                #pragma unroll
                for (int b = 0; b < 2; b++)
                    #pragma unroll
                    for (int r = 0; r < 4; r++) acc[a][b][r] = 0.f;
            #pragma unroll
            for (int kt = 0; kt < 5; kt++) {
                uint4 ah0 = abh[(kt * 2 + 0) * 32];
                uint4 ah1 = abh[(kt * 2 + 1) * 32];
                uint4 al0 = abl[(kt * 2 + 0) * 32];
                uint4 al1 = abl[(kt * 2 + 1) * 32];
                #pragma unroll
                for (int i2 = 0; i2 < 2; i2++) {
                    uint4 B = bgp[(i2 * 5 + kt) * 32];
                    mma16(acc[i2][0], ah0, B.x, B.y);
                    mma16(acc[i2][1], ah1, B.x, B.y);
                    mma16(acc[i2][0], al0, B.x, B.y);
                    mma16(acc[i2][1], al1, B.x, B.y);
                    mma16(acc[i2][0], ah0, B.z, B.w);
                    mma16(acc[i2][1], ah1, B.z, B.w);
                }
                if (hd) {
                    uint4 Bh = bh2[kt * 32];
                    mma16(facc[0], ah0, Bh.x, Bh.y);
                    mma16(facc[1], ah1, Bh.x, Bh.y);
                    mma16(facc[0], al0, Bh.x, Bh.y);
                    mma16(facc[1], al1, Bh.x, Bh.y);
                    mma16(facc[0], ah0, Bh.z, Bh.w);
                    mma16(facc[1], ah1, Bh.z, Bh.w);
                }
            }
        } else if (hd) {   // i == TT+1: heads only
            #pragma unroll
            for (int kt = 0; kt < 5; kt++) {
                uint4 ah0 = abh[(kt * 2 + 0) * 32];
                uint4 ah1 = abh[(kt * 2 + 1) * 32];
                uint4 al0 = abl[(kt * 2 + 0) * 32];
                uint4 al1 = abl[(kt * 2 + 1) * 32];
                uint4 Bh = bh2[kt * 32];
                mma16(facc[0], ah0, Bh.x, Bh.y);
                mma16(facc[1], ah1, Bh.x, Bh.y);
                mma16(facc[0], al0, Bh.x, Bh.y);
                mma16(facc[1], al1, Bh.x, Bh.y);
                mma16(facc[0], ah0, Bh.z, Bh.w);
                mma16(facc[1], ah1, Bh.z, Bh.w);
            }
        }

        // ======== pointwise LSTM ========
        float hreg[4];
        if (gt) {
            #pragma unroll
            for (int j = 0; j < 4; j++) {
                int mt = j >> 1, rh = j & 1;
                float gi = acc[0][mt][2 * rh + 0] + G0r[j][0];
                float gf = acc[0][mt][2 * rh + 1] + G0r[j][1];
                float gg = acc[1][mt][2 * rh + 0] + G0r[j][2];
                float go = acc[1][mt][2 * rh + 1] + G0r[j][3];
                float cc = sigg(gf) * c[j] + sigg(gi) * tanhg(gg);
                c[j] = cc;
                hreg[j] = sigg(go) * tanhg(cc);
            }
        }
        __syncthreads();   // all A / Po / DT reads done

        // ======== writes: A = h_i (paired words), d(i-1), DT, Po ========
        if (gt) {
            #pragma unroll
            for (int j = 0; j < 4; j++) {
                float hv = hreg[j];
                float hp = __shfl_xor_sync(0xFFFFFFFFu, hv, 1);
                if ((m4 & 1) == 0) {
                    __nv_bfloat16 b0 = __float2bfloat16(hv);
                    __nv_bfloat16 b1 = __float2bfloat16(hp);
                    float r0 = hv - __bfloat162float(b0);
                    float r1 = hp - __bfloat162float(b1);
                    int mt = j >> 1;
                    int s = sr + (j & 1) * 8 + mt * 16;
                    int rr = s & 15;
                    int lanew = (rr & 7) * 4 + lane_w;
                    int reg = (rr >> 3) + reg_b;
                    int idx = ((kt2 * 2 + mt) * 32 + lanew) * 4 + reg;
                    smu[SM_ABH + idx] = (uint32_t)__bfloat16_as_ushort(b0)
                                      | ((uint32_t)__bfloat16_as_ushort(b1) << 16);
                    smu[SM_ABL + idx] = packbf2(r0, r1);
                }
            }
            if (tid < 32) {
                int s = lane;
                sm[SM_DT + (i & 1) * 64 + s * 2]     = pdx;
                sm[SM_DT + (i & 1) * 64 + s * 2 + 1] = pdy;
                int mt = s >> 4, rr = s & 15;
                int idxd = (((4 * 2 + mt) * 32 + (rr & 7) * 4) * 4 + (rr >> 3));
                float rx, ry;
                {
                    __nv_bfloat16 hx = __float2bfloat16(pdx);
                    __nv_bfloat16 hy = __float2bfloat16(pdy);
                    rx = pdx - __bfloat162float(hx);
                    ry = pdy - __bfloat162float(hy);
                }
                smu[SM_ABH + idxd] = packbf2(pdx, pdy);
                smu[SM_ABL + idxd] = packbf2(rx, ry);
            }
        }
        if (hd) {
            int jc = 8 * warp + 2 * m4;
            #pragma unroll
            for (int mt = 0; mt < 2; mt++) {
                int r0 = sr + 16 * mt;
                *(float2*)(sm + SM_PO + r0 * 100 + jc) =
                    make_float2(facc[mt][0], facc[mt][1]);
                *(float2*)(sm + SM_PO + (r0 + 8) * 100 + jc) =
                    make_float2(facc[mt][2], facc[mt][3]);
            }
        }
        __syncthreads();   // new A / DT / Po visible

        // ======== GMM + LSE for step i-1 (overlaps next iter's mma) ========
        if (i >= 2) {
            int gs = 2 * warp + sh;
            float txv = sm[SM_DT + ((i + 1) & 1) * 64 + gs * 2];
            float tyv = sm[SM_DT + ((i + 1) & 1) * 64 + gs * 2 + 1];
            const float* pr = sm + SM_PO + gs * 100;
            float pi  = pr[gc];
            float2 mu  = *(const float2*)(pr + 16 + 2 * gc);
            float2 lsv = *(const float2*)(pr + 48 + 2 * gc);
            float corr = tanhg(pr[80 + gc]);
            float ls0 = fminf(fmaxf(lsv.x, -10.f), 10.f);
            float ls1 = fminf(fmaxf(lsv.y, -10.f), 10.f);
            float dx = txv - mu.x, dy = tyv - mu.y;
            float z0 = dx * __expf(-ls0);
            float z1 = dy * __expf(-ls1);
            float omr  = 1.f - corr * corr;
            float quad = z0 * z0 + z1 * z1 - 2.f * corr * z0 * z1;
            float cv = -1.8378770664093453f - (ls0 + ls1)
                       - 0.5f * __logf(omr) - 0.5f * __fdividef(quad, omr);
            float a = pi + cv;
            float b2 = pi;
            float ma = a, mb = b2;
            #pragma unroll
            for (int xm = 1; xm < 16; xm <<= 1) {
                ma = fmaxf(ma, __shfl_xor_sync(0xFFFFFFFFu, ma, xm));
                mb = fmaxf(mb, __shfl_xor_sync(0xFFFFFFFFu, mb, xm));
            }
            float ea = __expf(a - ma);
            float eb = __expf(b2 - mb);
            #pragma unroll
            for (int xm = 1; xm < 16; xm <<= 1) {
                ea += __shfl_xor_sync(0xFFFFFFFFu, ea, xm);
                eb += __shfl_xor_sync(0xFFFFFFFFu, eb, xm);
            }
            float lp = (ma + __logf(ea)) - (mb + __logf(eb));
            lacc += fminf(lp, 50.f);
        }
        // no trailing barrier: Po/DT next rewritten only after the next
        // iteration's first __syncthreads.
    }

    if ((lane & 15) == 0) out[nb + 2 * warp + sh] = lacc;
}

// ---------------------------------------------------------------------------
extern "C" void kernel_launch(void* const* d_in, const int* in_sizes, int n_in,
                              void* d_out, int out_size)
{
    const float* x      = (const float*)d_in[0];
    const float* z      = (const float*)d_in[1];
    const float* inps   = (const float*)d_in[2];
    const float* preds  = (const float*)d_in[3];
    const float* Wh0    = (const float*)d_in[4];
    const float* bh0    = (const float*)d_in[5];
    const float* Wc0    = (const float*)d_in[6];
    const float* bc0    = (const float*)d_in[7];
    const float* Wih    = (const float*)d_in[8];
    const float* Whh    = (const float*)d_in[9];
    const float* bih    = (const float*)d_in[10];
    const float* bhh    = (const float*)d_in[11];
    const float* Wpi    = (const float*)d_in[12];
    const float* bpi    = (const float*)d_in[13];
    const float* Wmu    = (const float*)d_in[14];
    const float* bmu    = (const float*)d_in[15];
    const float* Wls    = (const float*)d_in[16];
    const float* bls    = (const float*)d_in[17];
    const float* Wcorr  = (const float*)d_in[18];
    const float* bcorr  = (const float*)d_in[19];
    float* out = (float*)d_out;

    cudaFuncSetAttribute(phase1_kernel,
                         cudaFuncAttributeMaxDynamicSharedMemorySize, SMEM1);
    cudaFuncSetAttribute(phase2_kernel,
                         cudaFuncAttributeMaxDynamicSharedMemorySize, SMEM_BYTES);

    dim3 g1(NSEQ / 128, 384 / 96);
    phase1_kernel<<<g1, 256, SMEM1>>>(x, z, Wih, Wh0, Wc0, bih, bhh, bh0, bc0);

    phase2_kernel<<<NSEQ / 32, NTH, SMEM_BYTES>>>(
        inps, preds, Whh, Wih,
        Wpi, bpi, Wmu, bmu, Wls, bls, Wcorr, bcorr, out);
}